// round 16
// baseline (speedup 1.0000x reference)
#include <cuda_runtime.h>

#define B_  4
#define O_  32
#define C_  32
#define HW_ 32
#define P_  5
#define T_  288           // taps per output channel
#define EPSF 1e-6f
#define TSP_ 34           // pair-row stride in u64 (even -> 16B-aligned LDS.128)

typedef unsigned long long u64;

#define TILE_U64   (6 * TSP_)                    // 204 u64 per tile
#define TAB_BYTES  (T_ * 6 * 16)                 // 27648
#define TILES_BYTES (8 * 2 * TILE_U64 * 8)       // 26112 (2 buffers/warp)
#define SMEM_BYTES (TAB_BYTES + TILES_BYTES + 16)

__device__ __forceinline__ u64 pk(float lo, float hi) {
    u64 r; asm("mov.b64 %0, {%1, %2};" : "=l"(r) : "f"(lo), "f"(hi)); return r;
}
__device__ __forceinline__ void upk(float& lo, float& hi, u64 v) {
    asm("mov.b64 {%0, %1}, %2;" : "=f"(lo), "=f"(hi) : "l"(v));
}
__device__ __forceinline__ u64 fma2(u64 a, u64 b, u64 c) {
    u64 d; asm("fma.rn.f32x2 %0, %1, %2, %3;" : "=l"(d) : "l"(a), "l"(b), "l"(c));
    return d;
}
__device__ __forceinline__ u64 add2(u64 a, u64 b) {
    u64 d; asm("add.rn.f32x2 %0, %1, %2;" : "=l"(d) : "l"(a), "l"(b));
    return d;
}
// Per-half saturate via rt-1 immediate-form FFMA.SAT (validated, rel_err ~3e-7)
__device__ __forceinline__ u64 sat2(u64 u) {
    u64 s;
    asm("{\n\t"
        ".reg .f32 lo, hi;\n\t"
        "mov.b64 {lo, hi}, %1;\n\t"
        "fma.rn.sat.f32 lo, lo, 0f3F800000, 0f00000000;\n\t"
        "fma.rn.sat.f32 hi, hi, 0f3F800000, 0f00000000;\n\t"
        "mov.b64 %0, {lo, hi};\n\t"
        "}" : "=l"(s) : "l"(u));
    return s;
}
// 4-byte async copy global->shared; ok==0 => zero-fill (free boundary padding)
__device__ __forceinline__ void cpa4(unsigned dst, const float* src, int ok) {
    asm volatile("cp.async.ca.shared.global [%0], [%1], 4, %2;"
                 :: "r"(dst), "l"(src), "r"(ok ? 4 : 0) : "memory");
}

// ---------------------------------------------------------------------------
// R15 + EXPLICIT 2-buffer coefficient software pipeline:
// while tap t's 64 math instructions run, tap t+1's 6 coefficient vectors are
// loaded into the other register buffer (cA/cB rotation) — removes the
// ~29-cycle short-scoreboard wait R15 exposed at every tap boundary (profile:
// fma 44.6 / L1 53 / issue 51 with nothing saturated). FP order unchanged ->
// bit-identical numerics.
// Packed vertical pixel pairs (rows r, r+4 of an 8-row strip); all operands
// natively u64; cp.async double-buffered x tiles. Grid 512 = (b,o,strip);
// block 256 = 8 warps; warp = 4 channels, 8 px/thread. Dyn smem 52.5 KB.
// ---------------------------------------------------------------------------
__global__ __launch_bounds__(256, 3) void pc_fused(const float* __restrict__ x,
                                                   const float* __restrict__ pos,
                                                   const float* __restrict__ val,
                                                   float* __restrict__ out) {
    extern __shared__ __align__(16) char smem[];
    ulonglong2* s_tab  = reinterpret_cast<ulonglong2*>(smem);
    u64*        s_tile = reinterpret_cast<u64*>(smem + TAB_BYTES);
    float*      s_v0   = reinterpret_cast<float*>(s_tile);         // alias: dead
    u64*        red    = s_tile;                                   //  before use
    float*      s_bias = reinterpret_cast<float*>(smem + TAB_BYTES + TILES_BYTES);

    const int blk = blockIdx.x;
    const int quarter = blk & 3;           // 8-row strip
    const int o = (blk >> 2) & 31;
    const int b = blk >> 7;
    const int y0 = quarter * 8;

    const int tid = threadIdx.x;

    // ---- Phase 0: sort + duplicated coefficient tables ----
    const float* pbase = pos + o * (T_ * P_);
    const float* vbase = val + o * (T_ * P_);
#pragma unroll
    for (int rep = 0; rep < 2; rep++) {
        int ot = tid + rep * 256;
        if (ot < T_) {
            float p[P_], v[P_];
#pragma unroll
            for (int k = 0; k < P_; k++) { p[k] = pbase[ot * P_ + k]; v[k] = vbase[ot * P_ + k]; }
#define CE(a, bb) do { if (p[a] > p[bb]) { float t0 = p[a]; p[a] = p[bb]; p[bb] = t0; \
                                           float t1 = v[a]; v[a] = v[bb]; v[bb] = t1; } } while (0)
            CE(0,1); CE(3,4); CE(2,4); CE(2,3); CE(1,4); CE(0,3); CE(0,2); CE(1,3); CE(1,2);
#undef CE
            float* tf = (float*)(s_tab + ot * 6);   // 24 floats per tap
#pragma unroll
            for (int k = 0; k < 4; k++) {
                float den = p[k + 1] - p[k] + EPSF;
                float inv = 1.0f / den;
                float nq  = -p[k] * inv;
                float dv  = v[k + 1] - v[k];
                tf[4 * k + 0] = inv; tf[4 * k + 1] = inv;
                tf[4 * k + 2] = nq;  tf[4 * k + 3] = nq;
                tf[16 + 2 * k + 0] = dv; tf[16 + 2 * k + 1] = dv;
            }
            s_v0[ot] = v[0];
        }
    }
    __syncthreads();

    if (tid < 32) {        // bias = sum_t v0
        float s = 0.0f;
#pragma unroll
        for (int k = 0; k < 9; k++) s += s_v0[tid + k * 32];
#pragma unroll
        for (int off = 16; off > 0; off >>= 1) s += __shfl_down_sync(0xffffffffu, s, off);
        if (tid == 0) *s_bias = s;
    }
    __syncthreads();       // v0 alias dead from here; tiles may be written

    // ---- Phase 1 ----
    const int warp = tid >> 5;
    const int lane = tid & 31;
    const int rl   = lane >> 3;            // 0..3: pair row group (rows rl, rl+4)
    const int xg   = (lane & 7) * 4;       // 0,4,...,28
    const int gxc  = (lane >= 1) ? (lane - 1) : 0;

    u64 acc0 = 0ull, acc1 = 0ull, acc2 = 0ull, acc3 = 0ull;

    const float* xb = x + b * (C_ * HW_ * HW_);
    const int cBase = warp * 4;            // 4 channels per warp
    const float* xc = xb + cBase * (HW_ * HW_);
    u64* tA = s_tile + warp * 2 * TILE_U64;
    u64* tB = tA + TILE_U64;
    const unsigned tA32 = (unsigned)__cvta_generic_to_shared(tA);
    const unsigned tB32 = tA32 + TILE_U64 * 8;

    // constant OOB column 33 (gx=32): zero once for both buffers
    if (lane < 6) { tA[lane * TSP_ + 33] = 0ull; tB[lane * TSP_ + 33] = 0ull; }

// Async fill of one packed tile: pair-row k = (x[y0+k-1], x[y0+k+3]), col gx.
#define FILLA(TD, XC) do {                                                 \
    const float* xp_ = (XC);                                               \
    _Pragma("unroll")                                                      \
    for (int k = 0; k < 6; k++) {                                          \
        int gyL_ = y0 + k - 1;                                             \
        int gyH_ = y0 + k + 3;                                             \
        int okL_ = (lane >= 1) && (gyL_ >= 0);                             \
        int okH_ = (lane >= 1) && (gyH_ < HW_);                            \
        unsigned d_ = (TD) + (unsigned)((k * TSP_ + lane) * 8);            \
        cpa4(d_,     xp_ + (gyL_ >= 0 ? gyL_ : 0) * HW_ + gxc, okL_);      \
        cpa4(d_ + 4, xp_ + (gyH_ < HW_ ? gyH_ : 0) * HW_ + gxc, okH_);     \
    }                                                                      \
    if (lane < 6) {                                                        \
        int gyL_ = y0 + lane - 1;                                          \
        int gyH_ = y0 + lane + 3;                                          \
        unsigned d_ = (TD) + (unsigned)((lane * TSP_ + 32) * 8);           \
        cpa4(d_,     xp_ + (gyL_ >= 0 ? gyL_ : 0) * HW_ + 31, gyL_ >= 0);  \
        cpa4(d_ + 4, xp_ + (gyH_ < HW_ ? gyH_ : 0) * HW_ + 31, gyH_ < HW_);\
    }                                                                      \
    asm volatile("cp.async.commit_group;" ::: "memory");                   \
} while (0)

// One segment, 4 pixel-pairs: FFMA2 + sat2 + FFMA2 each.
#define SEG(XP, JJ, IV2, NQ2, DV2) do {                                    \
        u64 u0 = fma2((XP)[(JJ) + 0], (IV2), (NQ2));                       \
        u64 u1 = fma2((XP)[(JJ) + 1], (IV2), (NQ2));                       \
        u64 u2 = fma2((XP)[(JJ) + 2], (IV2), (NQ2));                       \
        u64 u3 = fma2((XP)[(JJ) + 3], (IV2), (NQ2));                       \
        u0 = sat2(u0);                                                     \
        u1 = sat2(u1);                                                     \
        u2 = sat2(u2);                                                     \
        u3 = sat2(u3);                                                     \
        acc0 = fma2(u0, (DV2), acc0);                                      \
        acc1 = fma2(u1, (DV2), acc1);                                      \
        acc2 = fma2(u2, (DV2), acc2);                                      \
        acc3 = fma2(u3, (DV2), acc3);                                      \
    } while (0)

// Full tap (4 segments) using coefficient buffer C (6 ulonglong2).
#define TAP(XP, JJ, Cb) do {                                               \
        SEG(XP, JJ, Cb[0].x, Cb[0].y, Cb[4].x);                            \
        SEG(XP, JJ, Cb[1].x, Cb[1].y, Cb[4].y);                            \
        SEG(XP, JJ, Cb[2].x, Cb[2].y, Cb[5].x);                            \
        SEG(XP, JJ, Cb[3].x, Cb[3].y, Cb[5].y);                            \
    } while (0)

#define LOADC(Cb, TP) do {                                                 \
        Cb[0] = (TP)[0]; Cb[1] = (TP)[1]; Cb[2] = (TP)[2];                 \
        Cb[3] = (TP)[3]; Cb[4] = (TP)[4]; Cb[5] = (TP)[5];                 \
    } while (0)

#define LOADXP(XP, CUR, ROW) do {                                          \
        const ulonglong2* rp_ =                                            \
            reinterpret_cast<const ulonglong2*>((CUR) + (ROW) * TSP_ + xg);\
        ulonglong2 a_ = rp_[0], b_ = rp_[1], c_ = rp_[2];                  \
        (XP)[0] = a_.x; (XP)[1] = a_.y; (XP)[2] = b_.x;                    \
        (XP)[3] = b_.y; (XP)[4] = c_.x; (XP)[5] = c_.y;                    \
    } while (0)

    // prologue: fill channel 0 into tA
    FILLA(tA32, xc);
    asm volatile("cp.async.wait_group 0;" ::: "memory");
    __syncwarp();

#pragma unroll
    for (int cc = 0; cc < 4; cc++) {
        u64* cur = (cc & 1) ? tB : tA;
        unsigned nxt32 = (cc & 1) ? tA32 : tB32;

        if (cc < 3) FILLA(nxt32, xc + HW_ * HW_);   // overlaps math below
        xc += HW_ * HW_;

        const ulonglong2* tp = s_tab + (cBase + cc) * 54;

        // explicit 2-buffer coefficient rotation: tap t's math covers the
        // LDS latency of tap t+1's coefficient loads.
        u64 xp[6];
        ulonglong2 cAr[6], cBr[6];
        LOADXP(xp, cur, rl + 0);
        LOADC(cAr, tp);                        // tap 0
        LOADC(cBr, tp + 6);  TAP(xp, 0, cAr);  // t0 (i=0,jj=0)
        LOADC(cAr, tp + 12); TAP(xp, 1, cBr);  // t1
        LOADC(cBr, tp + 18); TAP(xp, 2, cAr);  // t2
        LOADXP(xp, cur, rl + 1);
        LOADC(cAr, tp + 24); TAP(xp, 0, cBr);  // t3
        LOADC(cBr, tp + 30); TAP(xp, 1, cAr);  // t4
        LOADC(cAr, tp + 36); TAP(xp, 2, cBr);  // t5
        LOADXP(xp, cur, rl + 2);
        LOADC(cBr, tp + 42); TAP(xp, 0, cAr);  // t6
        LOADC(cAr, tp + 48); TAP(xp, 1, cBr);  // t7
        TAP(xp, 2, cAr);                       // t8

        if (cc < 3) {
            asm volatile("cp.async.wait_group 0;" ::: "memory");
            __syncwarp();                  // next tile ready; prev reads done
        }
    }
#undef LOADXP
#undef LOADC
#undef TAP
#undef SEG
#undef FILLA

    // ---- Phase 2: reduce across the 8 warps (red aliases tiles) ----
    __syncthreads();                       // all tile reads done everywhere
    red[(warp * 32 + lane) * 4 + 0] = acc0;
    red[(warp * 32 + lane) * 4 + 1] = acc1;
    red[(warp * 32 + lane) * 4 + 2] = acc2;
    red[(warp * 32 + lane) * 4 + 3] = acc3;
    __syncthreads();

    if (tid < 32) {
        u64 r0 = 0ull, r1 = 0ull, r2 = 0ull, r3 = 0ull;
#pragma unroll
        for (int w = 0; w < 8; w++) {
            const ulonglong2* q = reinterpret_cast<const ulonglong2*>(red + (w * 32 + tid) * 4);
            ulonglong2 qa = q[0], qb = q[1];
            r0 = add2(r0, qa.x); r1 = add2(r1, qa.y);
            r2 = add2(r2, qb.x); r3 = add2(r3, qb.y);
        }
        float bias = *s_bias;
        u64 bias2 = pk(bias, bias);
        r0 = add2(r0, bias2); r1 = add2(r1, bias2);
        r2 = add2(r2, bias2); r3 = add2(r3, bias2);
        float l0, h0, l1, h1, l2, h2, l3, h3;
        upk(l0, h0, r0); upk(l1, h1, r1); upk(l2, h2, r2); upk(l3, h3, r3);
        int rlo = tid >> 3;
        int col0 = (tid & 7) * 4;
        int base = ((b * O_ + o) * HW_ + y0) * HW_;
        *reinterpret_cast<float4*>(out + base + rlo * HW_ + col0) =
            make_float4(l0, l1, l2, l3);
        *reinterpret_cast<float4*>(out + base + (rlo + 4) * HW_ + col0) =
            make_float4(h0, h1, h2, h3);
    }
}

extern "C" void kernel_launch(void* const* d_in, const int* in_sizes, int n_in,
                              void* d_out, int out_size) {
    const float* x   = (const float*)d_in[0];
    const float* pos = (const float*)d_in[1];
    const float* val = (const float*)d_in[2];
    float* out = (float*)d_out;

    cudaFuncSetAttribute(pc_fused, cudaFuncAttributeMaxDynamicSharedMemorySize,
                         SMEM_BYTES);
    pc_fused<<<B_ * O_ * 4, 256, SMEM_BYTES>>>(x, pos, val, out);
}

// round 17
// speedup vs baseline: 1.0106x; 1.0106x over previous
#include <cuda_runtime.h>

#define B_  4
#define O_  32
#define C_  32
#define HW_ 32
#define P_  5
#define EPSF 1e-6f
#define TSC_ 34           // tile row stride in u64 (pairs), 16B-aligned rows
#define TROWS_ 10         // 8-row strip + 1 halo row each side
#define TILE_U64 (TROWS_ * TSC_)               // 340
#define NCP_ 16                                 // channel pairs
#define TAB_BYTES (NCP_ * 9 * 96)               // 13824 (NO duplication)
#define TILES_BYTES (8 * 2 * TILE_U64 * 8)      // 43520
#define SMEM_BYTES (TAB_BYTES + TILES_BYTES + 16)

typedef unsigned long long u64;

__device__ __forceinline__ u64 pk(float lo, float hi) {
    u64 r; asm("mov.b64 %0, {%1, %2};" : "=l"(r) : "f"(lo), "f"(hi)); return r;
}
__device__ __forceinline__ void upk(float& lo, float& hi, u64 v) {
    asm("mov.b64 {%0, %1}, %2;" : "=f"(lo), "=f"(hi) : "l"(v));
}
__device__ __forceinline__ u64 fma2(u64 a, u64 b, u64 c) {
    u64 d; asm("fma.rn.f32x2 %0, %1, %2, %3;" : "=l"(d) : "l"(a), "l"(b), "l"(c));
    return d;
}
// Per-half saturate via rt-1 immediate-form FFMA.SAT (validated numerics)
__device__ __forceinline__ u64 sat2(u64 u) {
    u64 s;
    asm("{\n\t"
        ".reg .f32 lo, hi;\n\t"
        "mov.b64 {lo, hi}, %1;\n\t"
        "fma.rn.sat.f32 lo, lo, 0f3F800000, 0f00000000;\n\t"
        "fma.rn.sat.f32 hi, hi, 0f3F800000, 0f00000000;\n\t"
        "mov.b64 %0, {lo, hi};\n\t"
        "}" : "=l"(s) : "l"(u));
    return s;
}
// 4-byte async copy global->shared; ok==0 => zero-fill
__device__ __forceinline__ void cpa4(unsigned dst, const float* src, int ok) {
    asm volatile("cp.async.ca.shared.global [%0], [%1], 4, %2;"
                 :: "r"(dst), "l"(src), "r"(ok ? 4 : 0) : "memory");
}

// ---------------------------------------------------------------------------
// CHANNEL-packed kernel: each u64 lane-pair = (channel c, channel c+1) at the
// SAME pixel. Coefficient pairs (inv_c, inv_c+1) etc. are natural — no
// duplication: coefficient LDS wavefronts and table smem HALVE vs R14-16
// (L1tex was the top utilization at 52%). Accumulator = (sum_even, sum_odd),
// folded with one FADD at the end. Math per seg unchanged: FFMA2+sat2+FFMA2.
// Grid 512 = (b, o, 8-row strip); block 256 = 8 warps; warp w = channel pairs
// 2w, 2w+1 over the full strip; thread = 8 px (rows rl & rl+4, cols xg..xg+3)
// = 8 packed accumulator streams (ILP 8). cp.async double-buffered tiles.
// ---------------------------------------------------------------------------
__global__ __launch_bounds__(256, 3) void pc_fused(const float* __restrict__ x,
                                                   const float* __restrict__ pos,
                                                   const float* __restrict__ val,
                                                   float* __restrict__ out) {
    extern __shared__ __align__(16) char smem[];
    ulonglong2* s_tab  = reinterpret_cast<ulonglong2*>(smem);
    u64*        s_tile = reinterpret_cast<u64*>(smem + TAB_BYTES);
    float*      s_v0   = reinterpret_cast<float*>(s_tile);     // alias: dead
    float4*     red4   = reinterpret_cast<float4*>(s_tile);    //  before use
    float*      s_bias = reinterpret_cast<float*>(smem + TAB_BYTES + TILES_BYTES);

    const int blk = blockIdx.x;
    const int quarter = blk & 3;           // 8-row strip
    const int o = (blk >> 2) & 31;
    const int b = blk >> 7;
    const int y0 = quarter * 8;

    const int tid = threadIdx.x;

    // ---- Phase 0: per (channel-pair, tap): sort BOTH channels' tables and
    // build channel-paired coefficients (no duplication).
    // Slot k (k=0..3): {(inv_c0k, inv_c1k), (nq_c0k, nq_c1k)}
    // Slot 4: {(dv_c0_0, dv_c1_0), (dv_c0_1, dv_c1_1)}; Slot 5: dv2, dv3.
    if (tid < NCP_ * 9) {
        const int ct = tid / 9;            // channel pair
        const int tt = tid % 9;            // tap (i*3+j)
        float* tf = (float*)(s_tab + (ct * 9 + tt) * 6);
        float v0sum = 0.0f;
#pragma unroll
        for (int h = 0; h < 2; h++) {      // the two channels of the pair
            const int c = ct * 2 + h;
            const int ot = c * 9 + tt;     // tap index in (o, C*9) table
            const float* pb = pos + (o * 288 + ot) * P_;
            const float* vb = val + (o * 288 + ot) * P_;
            float p[P_], v[P_];
#pragma unroll
            for (int k = 0; k < P_; k++) { p[k] = pb[k]; v[k] = vb[k]; }
#define CE(a, bb) do { if (p[a] > p[bb]) { float t0 = p[a]; p[a] = p[bb]; p[bb] = t0; \
                                           float t1 = v[a]; v[a] = v[bb]; v[bb] = t1; } } while (0)
            CE(0,1); CE(3,4); CE(2,4); CE(2,3); CE(1,4); CE(0,3); CE(0,2); CE(1,3); CE(1,2);
#undef CE
#pragma unroll
            for (int k = 0; k < 4; k++) {
                float den = p[k + 1] - p[k] + EPSF;
                float inv = 1.0f / den;
                float nq  = -p[k] * inv;
                float dv  = v[k + 1] - v[k];
                tf[4 * k + 0 + h] = inv;   // (inv_c0, inv_c1)
                tf[4 * k + 2 + h] = nq;    // (nq_c0, nq_c1)
                tf[16 + 2 * k + h] = dv;   // dv pairs in slots 4,5
            }
            v0sum += v[0];
        }
        s_v0[tid] = v0sum;                 // 144 partials
    }
    __syncthreads();

    if (tid < 32) {        // bias = sum of 144 v0 partials
        float s = 0.0f;
#pragma unroll
        for (int k = 0; k < 5; k++) {
            int idx = tid + k * 32;
            if (idx < NCP_ * 9) s += s_v0[idx];
        }
#pragma unroll
        for (int off = 16; off > 0; off >>= 1) s += __shfl_down_sync(0xffffffffu, s, off);
        if (tid == 0) *s_bias = s;
    }
    __syncthreads();       // v0 alias dead; tiles may be written

    // ---- Phase 1 ----
    const int warp = tid >> 5;
    const int lane = tid & 31;
    const int rl   = lane >> 3;            // 0..3: thread's low row in strip
    const int xg   = (lane & 7) * 4;       // 0,4,...,28
    const int gxc  = (lane >= 1) ? (lane - 1) : 0;

    u64 acc0 = 0ull, acc1 = 0ull, acc2 = 0ull, acc3 = 0ull;   // row rl
    u64 acc4 = 0ull, acc5 = 0ull, acc6 = 0ull, acc7 = 0ull;   // row rl+4

    const float* xb = x + b * (C_ * HW_ * HW_);
    u64* tA = s_tile + warp * 2 * TILE_U64;
    u64* tB = tA + TILE_U64;
    const unsigned tA32 = (unsigned)__cvta_generic_to_shared(tA);
    const unsigned tB32 = tA32 + TILE_U64 * 8;

    // constant OOB column 33 (gx=32): zero once for both buffers
    if (lane < TROWS_) {
        tA[lane * TSC_ + 33] = 0ull;
        tB[lane * TSC_ + 33] = 0ull;
    }

// Async fill of one channel-paired tile for channel pair CT:
// tile[r][col] = (x[2CT][y0+r-1][col-1], x[2CT+1][y0+r-1][col-1])
#define FILLA(TD, CT) do {                                                 \
    const float* x0_ = xb + (2 * (CT)) * (HW_ * HW_);                      \
    const float* x1_ = x0_ + HW_ * HW_;                                    \
    _Pragma("unroll")                                                      \
    for (int r = 0; r < TROWS_; r++) {                                     \
        int gy_ = y0 + r - 1;                                              \
        int ok_ = (gy_ >= 0) && (gy_ < HW_) && (lane >= 1);                \
        int gc_ = (gy_ >= 0 && gy_ < HW_ ? gy_ : 0) * HW_ + gxc;           \
        unsigned d_ = (TD) + (unsigned)((r * TSC_ + lane) * 8);            \
        cpa4(d_,     x0_ + gc_, ok_);                                      \
        cpa4(d_ + 4, x1_ + gc_, ok_);                                      \
    }                                                                      \
    if (lane < TROWS_) {                                                   \
        int gy_ = y0 + lane - 1;                                           \
        int ok_ = (gy_ >= 0) && (gy_ < HW_);                               \
        int gc_ = (ok_ ? gy_ : 0) * HW_ + 31;                              \
        unsigned d_ = (TD) + (unsigned)((lane * TSC_ + 32) * 8);           \
        cpa4(d_,     x0_ + gc_, ok_);                                      \
        cpa4(d_ + 4, x1_ + gc_, ok_);                                      \
    }                                                                      \
    asm volatile("cp.async.commit_group;" ::: "memory");                   \
} while (0)

// One segment: 8 packed streams (4 low-row px + 4 high-row px).
#define SEG(IV2, NQ2, DV2) do {                                            \
        u64 u0 = fma2(xlo[jj + 0], (IV2), (NQ2));                          \
        u64 u1 = fma2(xlo[jj + 1], (IV2), (NQ2));                          \
        u64 u2 = fma2(xlo[jj + 2], (IV2), (NQ2));                          \
        u64 u3 = fma2(xlo[jj + 3], (IV2), (NQ2));                          \
        u64 u4 = fma2(xhi[jj + 0], (IV2), (NQ2));                          \
        u64 u5 = fma2(xhi[jj + 1], (IV2), (NQ2));                          \
        u64 u6 = fma2(xhi[jj + 2], (IV2), (NQ2));                          \
        u64 u7 = fma2(xhi[jj + 3], (IV2), (NQ2));                          \
        u0 = sat2(u0); u1 = sat2(u1); u2 = sat2(u2); u3 = sat2(u3);        \
        u4 = sat2(u4); u5 = sat2(u5); u6 = sat2(u6); u7 = sat2(u7);        \
        acc0 = fma2(u0, (DV2), acc0);                                      \
        acc1 = fma2(u1, (DV2), acc1);                                      \
        acc2 = fma2(u2, (DV2), acc2);                                      \
        acc3 = fma2(u3, (DV2), acc3);                                      \
        acc4 = fma2(u4, (DV2), acc4);                                      \
        acc5 = fma2(u5, (DV2), acc5);                                      \
        acc6 = fma2(u6, (DV2), acc6);                                      \
        acc7 = fma2(u7, (DV2), acc7);                                      \
    } while (0)

#define LOADX(XP, ROW) do {                                                \
        const ulonglong2* rp_ =                                            \
            reinterpret_cast<const ulonglong2*>(cur + (ROW) * TSC_ + xg);  \
        ulonglong2 a_ = rp_[0], b_ = rp_[1], c_ = rp_[2];                  \
        (XP)[0] = a_.x; (XP)[1] = a_.y; (XP)[2] = b_.x;                    \
        (XP)[3] = b_.y; (XP)[4] = c_.x; (XP)[5] = c_.y;                    \
    } while (0)

    // prologue: fill channel pair 2*warp into tA
    FILLA(tA32, 2 * warp);
    asm volatile("cp.async.wait_group 0;" ::: "memory");
    __syncwarp();

#pragma unroll
    for (int cp = 0; cp < 2; cp++) {
        u64* cur = (cp & 1) ? tB : tA;
        if (cp == 0) FILLA(tB32, 2 * warp + 1);      // overlaps math below

        const ulonglong2* tp = s_tab + (2 * warp + cp) * 54;
#pragma unroll
        for (int i = 0; i < 3; i++) {
            u64 xlo[6], xhi[6];
            LOADX(xlo, rl + i);            // rows rl+i and rl+4+i
            LOADX(xhi, rl + 4 + i);
#pragma unroll
            for (int jj = 0; jj < 3; jj++) {
                const ulonglong2* t6 = tp + (i * 3 + jj) * 6;
                ulonglong2 c0 = t6[0];     // {(inv pair),(nq pair)} broadcast
                ulonglong2 c1 = t6[1];
                ulonglong2 c2 = t6[2];
                ulonglong2 c3 = t6[3];
                ulonglong2 d01 = t6[4];    // dv pairs for segs 0,1
                ulonglong2 d23 = t6[5];    // dv pairs for segs 2,3
                SEG(c0.x, c0.y, d01.x);
                SEG(c1.x, c1.y, d01.y);
                SEG(c2.x, c2.y, d23.x);
                SEG(c3.x, c3.y, d23.y);
            }
        }

        if (cp == 0) {
            asm volatile("cp.async.wait_group 0;" ::: "memory");
            __syncwarp();
        }
    }
#undef LOADX
#undef SEG
#undef FILLA

    // ---- Phase 2: fold channel halves, reduce across the 8 warps ----
    float l0, h0, l1, h1, l2, h2, l3, h3;
    __syncthreads();                       // all tile reads done everywhere
    {
        float4 rlo, rhi;
        upk(l0, h0, acc0); rlo.x = l0 + h0;
        upk(l1, h1, acc1); rlo.y = l1 + h1;
        upk(l2, h2, acc2); rlo.z = l2 + h2;
        upk(l3, h3, acc3); rlo.w = l3 + h3;
        upk(l0, h0, acc4); rhi.x = l0 + h0;
        upk(l1, h1, acc5); rhi.y = l1 + h1;
        upk(l2, h2, acc6); rhi.z = l2 + h2;
        upk(l3, h3, acc7); rhi.w = l3 + h3;
        red4[warp * 64 + rl * 8 + (lane & 7)]       = rlo;   // row rl
        red4[warp * 64 + (rl + 4) * 8 + (lane & 7)] = rhi;   // row rl+4
    }
    __syncthreads();

    if (tid < 64) {
        float bias = *s_bias;
        float4 r0 = red4[0 * 64 + tid];
        float4 r1 = red4[1 * 64 + tid];
        float4 r2 = red4[2 * 64 + tid];
        float4 r3 = red4[3 * 64 + tid];
        float4 r4 = red4[4 * 64 + tid];
        float4 r5 = red4[5 * 64 + tid];
        float4 r6 = red4[6 * 64 + tid];
        float4 r7 = red4[7 * 64 + tid];
        float4 res;
        res.x = bias + ((r0.x + r1.x) + (r2.x + r3.x)) + ((r4.x + r5.x) + (r6.x + r7.x));
        res.y = bias + ((r0.y + r1.y) + (r2.y + r3.y)) + ((r4.y + r5.y) + (r6.y + r7.y));
        res.z = bias + ((r0.z + r1.z) + (r2.z + r3.z)) + ((r4.z + r5.z) + (r6.z + r7.z));
        res.w = bias + ((r0.w + r1.w) + (r2.w + r3.w)) + ((r4.w + r5.w) + (r6.w + r7.w));
        int row = tid >> 3;
        int col0 = (tid & 7) * 4;
        int oidx = ((b * O_ + o) * HW_ + y0 + row) * HW_ + col0;
        *reinterpret_cast<float4*>(out + oidx) = res;
    }
}

extern "C" void kernel_launch(void* const* d_in, const int* in_sizes, int n_in,
                              void* d_out, int out_size) {
    const float* x   = (const float*)d_in[0];
    const float* pos = (const float*)d_in[1];
    const float* val = (const float*)d_in[2];
    float* out = (float*)d_out;

    cudaFuncSetAttribute(pc_fused, cudaFuncAttributeMaxDynamicSharedMemorySize,
                         SMEM_BYTES);
    pc_fused<<<B_ * O_ * 4, 256, SMEM_BYTES>>>(x, pos, val, out);
}